// round 12
// baseline (speedup 1.0000x reference)
#include <cuda_runtime.h>
#include <cuda_bf16.h>

#define BATCH 4
#define NTOK  4096
#define CIN   512
#define DQK   64
#define DV    256
#define MTOT  (BATCH * NTOK)   // 16384
#define LOG2E 1.4426950408889634f

// Scratch (device globals; no runtime allocation allowed)
__device__ __align__(16) __nv_bfloat16 g_fb[MTOT * DQK];     // keys    bf16
__device__ __align__(16) __nv_bfloat16 g_gb[MTOT * DQK];     // queries bf16 (pre-scaled by log2e)
__device__ __align__(16) __nv_bfloat16 g_hb[MTOT * DV];      // values  bf16
__device__ __align__(16) __nv_bfloat16 g_ob[MTOT * DV];      // attn out bf16

// ---------------------------------------------------------------------------
// PTX helpers
// ---------------------------------------------------------------------------
__device__ __forceinline__ unsigned smaddr(const void* p) {
    return (unsigned)__cvta_generic_to_shared(p);
}
__device__ __forceinline__ void ldsm_x4(unsigned a, unsigned* r) {
    asm volatile("ldmatrix.sync.aligned.m8n8.x4.shared.b16 {%0,%1,%2,%3},[%4];"
                 : "=r"(r[0]), "=r"(r[1]), "=r"(r[2]), "=r"(r[3]) : "r"(a));
}
__device__ __forceinline__ void ldsm_x4_trans(unsigned a, unsigned* r) {
    asm volatile("ldmatrix.sync.aligned.m8n8.x4.trans.shared.b16 {%0,%1,%2,%3},[%4];"
                 : "=r"(r[0]), "=r"(r[1]), "=r"(r[2]), "=r"(r[3]) : "r"(a));
}
__device__ __forceinline__ void mma16816(float* c, const unsigned* a, const unsigned* b) {
    asm volatile(
        "mma.sync.aligned.m16n8k16.row.col.f32.bf16.bf16.f32 "
        "{%0,%1,%2,%3},{%4,%5,%6,%7},{%8,%9},{%0,%1,%2,%3};"
        : "+f"(c[0]), "+f"(c[1]), "+f"(c[2]), "+f"(c[3])
        : "r"(a[0]), "r"(a[1]), "r"(a[2]), "r"(a[3]), "r"(b[0]), "r"(b[1]));
}
__device__ __forceinline__ void cp_async16(void* smem_dst, const void* gmem_src) {
    asm volatile("cp.async.cg.shared.global [%0], [%1], 16;"
                 :: "r"(smaddr(smem_dst)), "l"(gmem_src));
}
__device__ __forceinline__ unsigned packbf(float a, float b) {
    __nv_bfloat162 t = __floats2bfloat162_rn(a, b);
    return *(unsigned*)&t;
}
__device__ __forceinline__ float exp2a(float x) {
    float y;
    asm("ex2.approx.f32 %0, %1;" : "=f"(y) : "f"(x));
    return y;
}

// ---------------------------------------------------------------------------
// Kernel 1: projection GEMM (EXACT R11 version — proven config)
// ---------------------------------------------------------------------------
#define AP 40
#define BPP 136
#define PROJ_NIT (CIN / 32)   // 16

__global__ __launch_bounds__(256) void proj_gemm(
    const float* __restrict__ x,
    const float* __restrict__ Wf, const float* __restrict__ Wg,
    const float* __restrict__ Wh,
    const float* __restrict__ bf, const float* __restrict__ bg,
    const float* __restrict__ bh)
{
    __shared__ __nv_bfloat16 As[2][128 * AP];
    __shared__ __nv_bfloat16 Bs[2][32 * BPP];

    const int tid  = threadIdx.x;
    const int lane = tid & 31;
    const int w    = tid >> 5;
    const int m0   = blockIdx.y * 128;
    const int n0   = blockIdx.x * 128;
    const int mw   = (w >> 1) * 32;
    const int nw   = (w & 1) * 64;

    const float* bsrc[4];
    int brow[4], bcol[4];
    int arow_[4], acol_[4];
    #pragma unroll
    for (int it = 0; it < 4; ++it) {
        int idx = tid + 256 * it;
        arow_[it] = idx >> 3; acol_[it] = (idx & 7) * 4;
        int r = idx >> 5, c = (idx & 31) * 4;
        brow[it] = r; bcol[it] = c;
        int nn = n0 + c;
        if (nn < 64)        bsrc[it] = Wf + nn;
        else if (nn < 128)  bsrc[it] = Wg + (nn - 64);
        else                bsrc[it] = Wh + (size_t)(nn - 128);
    }

    float4 aR[4], bR[4];
    auto ldg_tiles = [&](int k0) {
        #pragma unroll
        for (int it = 0; it < 4; ++it)
            aR[it] = *(const float4*)&x[(size_t)(m0 + arow_[it]) * CIN + k0 + acol_[it]];
        #pragma unroll
        for (int it = 0; it < 4; ++it) {
            int ld = (n0 + bcol[it] < 128) ? DQK : DV;
            bR[it] = *(const float4*)&bsrc[it][(size_t)(k0 + brow[it]) * ld];
        }
    };
    auto sts_tiles = [&](int buf) {
        #pragma unroll
        for (int it = 0; it < 4; ++it) {
            __nv_bfloat16* d = &As[buf][arow_[it] * AP + acol_[it]];
            *(__nv_bfloat162*)&d[0] = __floats2bfloat162_rn(aR[it].x, aR[it].y);
            *(__nv_bfloat162*)&d[2] = __floats2bfloat162_rn(aR[it].z, aR[it].w);
        }
        #pragma unroll
        for (int it = 0; it < 4; ++it) {
            __nv_bfloat16* d = &Bs[buf][brow[it] * BPP + bcol[it]];
            *(__nv_bfloat162*)&d[0] = __floats2bfloat162_rn(bR[it].x, bR[it].y);
            *(__nv_bfloat162*)&d[2] = __floats2bfloat162_rn(bR[it].z, bR[it].w);
        }
    };

    float acc[2][8][4];
    #pragma unroll
    for (int m = 0; m < 2; ++m)
        #pragma unroll
        for (int t = 0; t < 8; ++t)
            #pragma unroll
            for (int e = 0; e < 4; ++e) acc[m][t][e] = 0.0f;

    const int lrow = (lane & 7) + 8 * ((lane >> 3) & 1);
    const int lcol = 8 * (lane >> 4);

    ldg_tiles(0);
    sts_tiles(0);

    for (int k = 0; k < PROJ_NIT; ++k) {
        const int buf = k & 1;
        if (k + 1 < PROJ_NIT) ldg_tiles((k + 1) * 32);
        __syncthreads();

        unsigned af[2][2][4];
        #pragma unroll
        for (int m = 0; m < 2; ++m)
            #pragma unroll
            for (int kb = 0; kb < 2; ++kb)
                ldsm_x4(smaddr(&As[buf][(mw + m * 16 + lrow) * AP + kb * 16 + lcol]),
                        af[m][kb]);
        #pragma unroll
        for (int kb = 0; kb < 2; ++kb) {
            #pragma unroll
            for (int j = 0; j < 4; ++j) {
                unsigned bv[4];
                ldsm_x4_trans(smaddr(&Bs[buf][(kb * 16 + lrow) * BPP + nw + 16 * j + lcol]), bv);
                #pragma unroll
                for (int m = 0; m < 2; ++m) {
                    mma16816(acc[m][2 * j + 0], af[m][kb], bv + 0);
                    mma16816(acc[m][2 * j + 1], af[m][kb], bv + 2);
                }
            }
        }
        if (k + 1 < PROJ_NIT) sts_tiles(buf ^ 1);
    }

    const int gc = n0 + nw;
    __nv_bfloat16* out;
    const float* bias;
    int ldo, coff;
    float scl = 1.0f;
    if (gc < 64)        { out = g_fb; bias = bf; ldo = DQK; coff = 0; }
    else if (gc < 128)  { out = g_gb; bias = bg; ldo = DQK; coff = 64; scl = LOG2E; }
    else                { out = g_hb; bias = bh; ldo = DV;  coff = 128; }

    const int crow = lane >> 2;
    const int ccol = 2 * (lane & 3);
    #pragma unroll
    for (int m = 0; m < 2; ++m) {
        int r1 = m0 + mw + m * 16 + crow;
        int r2 = r1 + 8;
        #pragma unroll
        for (int t = 0; t < 8; ++t) {
            int col = gc - coff + 8 * t + ccol;
            float b0 = bias[col], b1 = bias[col + 1];
            *(__nv_bfloat162*)&out[(size_t)r1 * ldo + col] =
                __floats2bfloat162_rn((acc[m][t][0] + b0) * scl, (acc[m][t][1] + b1) * scl);
            *(__nv_bfloat162*)&out[(size_t)r2 * ldo + col] =
                __floats2bfloat162_rn((acc[m][t][2] + b0) * scl, (acc[m][t][3] + b1) * scl);
        }
    }
}

// ---------------------------------------------------------------------------
// Kernel 2: flash attention — software-pipelined across key tiles:
//   iter kt:  S-mma(kt+1) -> PV-mma(kt) -> exp(kt+1)
// so exp executes on FMA/MUFU pipes while the tensor pipe drains PV.
// 4 K/V buffers (prefetch distance 3), 1 __syncthreads per tile.
// ---------------------------------------------------------------------------
#define QP 72
#define KBUF 9216     // 64*72*2
#define VBUF 33792    // 64*264*2
#define VP 264

#define SM_Q  0                        // 18432
#define SM_K  18432                    // 4 x 9216
#define SM_V  (18432 + 4 * KBUF)       // 4 x 33792
#define ATTN_SMEM_BYTES (18432 + 4 * KBUF + 4 * VBUF)   // 190464

#define NTILE (NTOK / 64)   // 64

__global__ __launch_bounds__(256, 1) void attn_kernel()
{
    extern __shared__ char sm[];
    __nv_bfloat16* Qs = (__nv_bfloat16*)(sm + SM_Q);

    const int tid  = threadIdx.x;
    const int lane = tid & 31;
    const int w    = tid >> 5;
    const int b    = blockIdx.y;
    const int q0   = blockIdx.x * 128;

    const __nv_bfloat16* Fb = g_fb + (size_t)b * NTOK * DQK;
    const __nv_bfloat16* Gb = g_gb + (size_t)b * NTOK * DQK;
    const __nv_bfloat16* Hb = g_hb + (size_t)b * NTOK * DV;

    int kr[2], kc[2], vr[8], vc[8];
    #pragma unroll
    for (int it = 0; it < 2; ++it) {
        int idx = tid + 256 * it;
        kr[it] = idx >> 3; kc[it] = (idx & 7) * 8;
    }
    #pragma unroll
    for (int it = 0; it < 8; ++it) {
        int idx = tid + 256 * it;
        vr[it] = idx >> 5; vc[it] = (idx & 31) * 8;
    }

    auto prefetch = [&](int kt) {
        const __nv_bfloat16* Fk = Fb + (size_t)kt * 64 * DQK;
        const __nv_bfloat16* Hk = Hb + (size_t)kt * 64 * DV;
        const int s = kt & 3;
        __nv_bfloat16* Kd = (__nv_bfloat16*)(sm + SM_K + s * KBUF);
        __nv_bfloat16* Vd = (__nv_bfloat16*)(sm + SM_V + s * VBUF);
        #pragma unroll
        for (int it = 0; it < 2; ++it)
            cp_async16(&Kd[kr[it] * QP + kc[it]], &Fk[(size_t)kr[it] * DQK + kc[it]]);
        #pragma unroll
        for (int it = 0; it < 8; ++it)
            cp_async16(&Vd[vr[it] * VP + vc[it]], &Hk[(size_t)vr[it] * DV + vc[it]]);
        asm volatile("cp.async.commit_group;");
    };

    // Load Q tile (128 x 64 bf16)
    #pragma unroll
    for (int it = 0; it < 4; ++it) {
        int idx = tid + 256 * it;
        int r = idx >> 3, c = (idx & 7) * 8;
        *(uint4*)&Qs[r * QP + c] = *(const uint4*)&Gb[(size_t)(q0 + r) * DQK + c];
    }

    // Prologue: 3 tiles in flight
    prefetch(0);
    prefetch(1);
    prefetch(2);
    __syncthreads();   // Q visible

    const int arow   = w * 16 + (lane & 7) + 8 * ((lane >> 3) & 1);
    const int acolhi = 8 * (lane >> 4);
    unsigned qa[4][4];
    #pragma unroll
    for (int kb = 0; kb < 4; ++kb)
        ldsm_x4(smaddr(&Qs[arow * QP + kb * 16 + acolhi]), qa[kb]);

    float oacc[32][4];
    #pragma unroll
    for (int t = 0; t < 32; ++t)
        #pragma unroll
        for (int e = 0; e < 4; ++e) oacc[t][e] = 0.0f;

    float l0 = 0.0f, l1 = 0.0f;
    unsigned pa[4][4];

    // S-mma for a given smem K slot -> sacc
    auto s_mma = [&](int slot, float (*sacc)[4]) {
        const __nv_bfloat16* Ks = (const __nv_bfloat16*)(sm + SM_K + slot * KBUF);
        #pragma unroll
        for (int t = 0; t < 8; ++t)
            #pragma unroll
            for (int e = 0; e < 4; ++e) sacc[t][e] = 0.0f;
        #pragma unroll
        for (int kb = 0; kb < 4; ++kb) {
            const int kcc = kb * 16 + 8 * ((lane >> 3) & 1);
            #pragma unroll
            for (int h = 0; h < 4; ++h) {
                int nrow = h * 16 + (lane & 7) + 8 * (lane >> 4);
                unsigned bb[4];
                ldsm_x4(smaddr(&Ks[nrow * QP + kcc]), bb);
                mma16816(sacc[2 * h + 0], qa[kb], bb + 0);
                mma16816(sacc[2 * h + 1], qa[kb], bb + 2);
            }
        }
    };
    auto exp_pack = [&](float (*sacc)[4]) {
        #pragma unroll
        for (int j = 0; j < 8; ++j) {
            sacc[j][0] = exp2a(sacc[j][0]);
            sacc[j][1] = exp2a(sacc[j][1]);
            sacc[j][2] = exp2a(sacc[j][2]);
            sacc[j][3] = exp2a(sacc[j][3]);
            l0 += sacc[j][0] + sacc[j][1];
            l1 += sacc[j][2] + sacc[j][3];
        }
        #pragma unroll
        for (int kb = 0; kb < 4; ++kb) {
            pa[kb][0] = packbf(sacc[2 * kb][0],     sacc[2 * kb][1]);
            pa[kb][1] = packbf(sacc[2 * kb][2],     sacc[2 * kb][3]);
            pa[kb][2] = packbf(sacc[2 * kb + 1][0], sacc[2 * kb + 1][1]);
            pa[kb][3] = packbf(sacc[2 * kb + 1][2], sacc[2 * kb + 1][3]);
        }
    };

    // Prologue compute: S(0) -> pa(0)
    {
        asm volatile("cp.async.wait_group 2;");   // tile 0 ready
        __syncthreads();
        float sacc[8][4];
        s_mma(0, sacc);
        exp_pack(sacc);
    }

    for (int kt = 0; kt < NTILE; ++kt) {
        // Ensure tiles <= kt+1 complete (newest pending group may be kt+2)
        if (kt + 2 < NTILE) asm volatile("cp.async.wait_group 1;");
        else                asm volatile("cp.async.wait_group 0;");
        __syncthreads();   // all warps done iter kt-1; tile data visible

        if (kt + 3 < NTILE) prefetch(kt + 3);   // slot (kt-1)&3, safe after barrier

        float sacc[8][4];
        if (kt + 1 < NTILE) s_mma((kt + 1) & 3, sacc);   // S for NEXT tile

        // ---- O += P(kt) @ V(kt) : tensor pipe drains while exp below runs ----
        const __nv_bfloat16* Vs = (const __nv_bfloat16*)(sm + SM_V + (kt & 3) * VBUF);
        #pragma unroll
        for (int kb = 0; kb < 4; ++kb) {
            int vrow = kb * 16 + (lane & 7) + 8 * ((lane >> 3) & 1);
            #pragma unroll
            for (int j = 0; j < 16; ++j) {
                unsigned bv[4];
                ldsm_x4_trans(smaddr(&Vs[vrow * VP + 16 * j + 8 * (lane >> 4)]), bv);
                mma16816(oacc[2 * j + 0], pa[kb], bv + 0);
                mma16816(oacc[2 * j + 1], pa[kb], bv + 2);
            }
        }

        if (kt + 1 < NTILE) exp_pack(sacc);   // overlaps PV tensor drain
    }

    l0 += __shfl_xor_sync(0xffffffffu, l0, 1);
    l0 += __shfl_xor_sync(0xffffffffu, l0, 2);
    l1 += __shfl_xor_sync(0xffffffffu, l1, 1);
    l1 += __shfl_xor_sync(0xffffffffu, l1, 2);

    const int crow = lane >> 2;
    const int ccol = 2 * (lane & 3);
    __nv_bfloat16* Op = g_ob + (size_t)b * NTOK * DV;
    const int r1 = q0 + w * 16 + crow;
    const int r2 = r1 + 8;
    const float inv0 = 1.0f / l0;
    const float inv1 = 1.0f / l1;
    #pragma unroll
    for (int t = 0; t < 32; ++t) {
        int c = 8 * t + ccol;
        *(__nv_bfloat162*)&Op[(size_t)r1 * DV + c] =
            __floats2bfloat162_rn(oacc[t][0] * inv0, oacc[t][1] * inv0);
        *(__nv_bfloat162*)&Op[(size_t)r2 * DV + c] =
            __floats2bfloat162_rn(oacc[t][2] * inv1, oacc[t][3] * inv1);
    }
}

// ---------------------------------------------------------------------------
// Kernel 3: output projection (EXACT R11 version)
// ---------------------------------------------------------------------------
#define OUT_NIT (DV / 32)    // 8

__global__ __launch_bounds__(256) void outproj_gemm(
    const float* __restrict__ x, const float* __restrict__ Wo,
    const float* __restrict__ bo, const float* __restrict__ gamma,
    float* __restrict__ out)
{
    __shared__ __nv_bfloat16 As[2][128 * AP];
    __shared__ __nv_bfloat16 Bs[2][32 * BPP];

    const int tid  = threadIdx.x;
    const int lane = tid & 31;
    const int w    = tid >> 5;
    const int m0   = blockIdx.y * 128;
    const int n0   = blockIdx.x * 128;
    const int mw   = (w >> 1) * 32;
    const int nw   = (w & 1) * 64;

    const __nv_bfloat16* agp[2];
    unsigned asmoff[2];
    const float* bgp[4];
    int bsoff[4];
    #pragma unroll
    for (int it = 0; it < 2; ++it) {
        int idx = tid + 256 * it;
        int r = idx >> 2, c = (idx & 3) * 8;
        agp[it]    = g_ob + (size_t)(m0 + r) * DV + c;
        asmoff[it] = r * AP + c;
    }
    #pragma unroll
    for (int it = 0; it < 4; ++it) {
        int idx = tid + 256 * it;
        int r = idx >> 5, c = (idx & 31) * 4;
        bgp[it]   = Wo + (size_t)r * CIN + n0 + c;
        bsoff[it] = r * BPP + c;
    }

    float4 bR[4];
    auto cp_a = [&](int buf) {
        #pragma unroll
        for (int it = 0; it < 2; ++it) {
            cp_async16(&As[buf][asmoff[it]], agp[it]);
            agp[it] += 32;
        }
        asm volatile("cp.async.commit_group;");
    };
    auto ldg_b = [&]() {
        #pragma unroll
        for (int it = 0; it < 4; ++it) { bR[it] = *(const float4*)bgp[it]; bgp[it] += 32 * CIN; }
    };
    auto sts_b = [&](int buf) {
        #pragma unroll
        for (int it = 0; it < 4; ++it) {
            __nv_bfloat16* d = &Bs[buf][bsoff[it]];
            *(__nv_bfloat162*)&d[0] = __floats2bfloat162_rn(bR[it].x, bR[it].y);
            *(__nv_bfloat162*)&d[2] = __floats2bfloat162_rn(bR[it].z, bR[it].w);
        }
    };

    float acc[2][8][4];
    #pragma unroll
    for (int m = 0; m < 2; ++m)
        #pragma unroll
        for (int t = 0; t < 8; ++t)
            #pragma unroll
            for (int e = 0; e < 4; ++e) acc[m][t][e] = 0.0f;

    const int lrow = (lane & 7) + 8 * ((lane >> 3) & 1);
    const int lcol = 8 * (lane >> 4);

    ldg_b();
    cp_a(0);
    sts_b(0);

    for (int k = 0; k < OUT_NIT; ++k) {
        const int buf = k & 1;
        if (k + 1 < OUT_NIT) {
            ldg_b();
            cp_a(buf ^ 1);
            asm volatile("cp.async.wait_group 1;");
        } else {
            asm volatile("cp.async.wait_group 0;");
        }
        __syncthreads();

        unsigned af[2][2][4];
        #pragma unroll
        for (int m = 0; m < 2; ++m)
            #pragma unroll
            for (int kb = 0; kb < 2; ++kb)
                ldsm_x4(smaddr(&As[buf][(mw + m * 16 + lrow) * AP + kb * 16 + lcol]),
                        af[m][kb]);
        #pragma unroll
        for (int kb = 0; kb < 2; ++kb) {
            #pragma unroll
            for (int j = 0; j < 4; ++j) {
                unsigned bv[4];
                ldsm_x4_trans(smaddr(&Bs[buf][(kb * 16 + lrow) * BPP + nw + 16 * j + lcol]), bv);
                #pragma unroll
                for (int m = 0; m < 2; ++m) {
                    mma16816(acc[m][2 * j + 0], af[m][kb], bv + 0);
                    mma16816(acc[m][2 * j + 1], af[m][kb], bv + 2);
                }
            }
        }
        if (k + 1 < OUT_NIT) sts_b(buf ^ 1);
    }

    const float ga = gamma[0];
    const int crow = lane >> 2;
    const int ccol = 2 * (lane & 3);
    #pragma unroll
    for (int m = 0; m < 2; ++m) {
        int r1 = m0 + mw + m * 16 + crow;
        int r2 = r1 + 8;
        #pragma unroll
        for (int t = 0; t < 8; ++t) {
            int col = n0 + nw + 8 * t + ccol;
            float b0 = bo[col], b1 = bo[col + 1];
            size_t i1 = (size_t)r1 * CIN + col;
            size_t i2 = (size_t)r2 * CIN + col;
            float2 x1 = *(const float2*)&x[i1];
            float2 x2 = *(const float2*)&x[i2];
            *(float2*)&out[i1] = make_float2(x1.x + ga * (acc[m][t][0] + b0),
                                             x1.y + ga * (acc[m][t][1] + b1));
            *(float2*)&out[i2] = make_float2(x2.x + ga * (acc[m][t][2] + b0),
                                             x2.y + ga * (acc[m][t][3] + b1));
        }
    }
}

// ---------------------------------------------------------------------------
extern "C" void kernel_launch(void* const* d_in, const int* in_sizes, int n_in,
                              void* d_out, int out_size)
{
    const float* x     = (const float*)d_in[0];
    const float* Wf    = (const float*)d_in[1];
    const float* bf    = (const float*)d_in[2];
    const float* Wg    = (const float*)d_in[3];
    const float* bg    = (const float*)d_in[4];
    const float* Wh    = (const float*)d_in[5];
    const float* bh    = (const float*)d_in[6];
    const float* Wo    = (const float*)d_in[7];
    const float* bo    = (const float*)d_in[8];
    const float* gamma = (const float*)d_in[9];
    float* out = (float*)d_out;

    cudaFuncSetAttribute(attn_kernel,
                         cudaFuncAttributeMaxDynamicSharedMemorySize,
                         ATTN_SMEM_BYTES);

    proj_gemm<<<dim3(3, 128), 256>>>(x, Wf, Wg, Wh, bf, bg, bh);
    attn_kernel<<<dim3(NTOK / 128, BATCH), 256, ATTN_SMEM_BYTES>>>();
    outproj_gemm<<<dim3(4, 128), 256>>>(x, Wo, bo, gamma, out);
}

// round 13
// speedup vs baseline: 1.0493x; 1.0493x over previous
#include <cuda_runtime.h>
#include <cuda_bf16.h>

#define BATCH 4
#define NTOK  4096
#define CIN   512
#define DQK   64
#define DV    256
#define MTOT  (BATCH * NTOK)   // 16384
#define NPROJ 384
#define LOG2E 1.4426950408889634f

// Scratch (device globals; no runtime allocation allowed)
__device__ __align__(16) __nv_bfloat16 g_wb[CIN * NPROJ];    // [Wf|Wg|Wh] bf16
__device__ __align__(16) __nv_bfloat16 g_wob[DV * CIN];      // Wo bf16
__device__ __align__(16) __nv_bfloat16 g_fb[MTOT * DQK];     // keys    bf16
__device__ __align__(16) __nv_bfloat16 g_gb[MTOT * DQK];     // queries bf16 (pre-scaled by log2e)
__device__ __align__(16) __nv_bfloat16 g_hb[MTOT * DV];      // values  bf16
__device__ __align__(16) __nv_bfloat16 g_ob[MTOT * DV];      // attn out bf16

// ---------------------------------------------------------------------------
// PTX helpers
// ---------------------------------------------------------------------------
__device__ __forceinline__ unsigned smaddr(const void* p) {
    return (unsigned)__cvta_generic_to_shared(p);
}
__device__ __forceinline__ void ldsm_x4(unsigned a, unsigned* r) {
    asm volatile("ldmatrix.sync.aligned.m8n8.x4.shared.b16 {%0,%1,%2,%3},[%4];"
                 : "=r"(r[0]), "=r"(r[1]), "=r"(r[2]), "=r"(r[3]) : "r"(a));
}
__device__ __forceinline__ void ldsm_x4_trans(unsigned a, unsigned* r) {
    asm volatile("ldmatrix.sync.aligned.m8n8.x4.trans.shared.b16 {%0,%1,%2,%3},[%4];"
                 : "=r"(r[0]), "=r"(r[1]), "=r"(r[2]), "=r"(r[3]) : "r"(a));
}
__device__ __forceinline__ void mma16816(float* c, const unsigned* a, const unsigned* b) {
    asm volatile(
        "mma.sync.aligned.m16n8k16.row.col.f32.bf16.bf16.f32 "
        "{%0,%1,%2,%3},{%4,%5,%6,%7},{%8,%9},{%0,%1,%2,%3};"
        : "+f"(c[0]), "+f"(c[1]), "+f"(c[2]), "+f"(c[3])
        : "r"(a[0]), "r"(a[1]), "r"(a[2]), "r"(a[3]), "r"(b[0]), "r"(b[1]));
}
__device__ __forceinline__ void cp_async16(void* smem_dst, const void* gmem_src) {
    asm volatile("cp.async.cg.shared.global [%0], [%1], 16;"
                 :: "r"(smaddr(smem_dst)), "l"(gmem_src));
}
__device__ __forceinline__ unsigned packbf(float a, float b) {
    __nv_bfloat162 t = __floats2bfloat162_rn(a, b);
    return *(unsigned*)&t;
}
__device__ __forceinline__ float exp2a(float x) {
    float y;
    asm("ex2.approx.f32 %0, %1;" : "=f"(y) : "f"(x));
    return y;
}

// ---------------------------------------------------------------------------
// Prep: pack [Wf|Wg|Wh] -> g_wb (512x384), Wo -> g_wob (256x512), bf16.
// 327680 elements total, grid 640 x 512.
// ---------------------------------------------------------------------------
__global__ __launch_bounds__(512) void pack_w_kernel(
    const float* __restrict__ Wf, const float* __restrict__ Wg,
    const float* __restrict__ Wh, const float* __restrict__ Wo)
{
    int i = blockIdx.x * 512 + threadIdx.x;
    const int NW = CIN * NPROJ;   // 196608
    if (i < NW) {
        int k = i / NPROJ, n = i % NPROJ;
        float v;
        if (n < 64)       v = Wf[k * DQK + n];
        else if (n < 128) v = Wg[k * DQK + (n - 64)];
        else              v = Wh[k * DV + (n - 128)];
        g_wb[i] = __float2bfloat16(v);
    } else {
        int j = i - NW;   // < 131072
        g_wob[j] = __float2bfloat16(Wo[j]);
    }
}

// ---------------------------------------------------------------------------
// Kernel 1: projection GEMM. A: x fp32 register-staged + cvt (proven path).
// B: bf16 cp.async from g_wb (uniform ld=384) — no register staging, no
// per-iter source select. grid=(3,128), BM=128 BN=128 BK=32, 8 warps.
// ---------------------------------------------------------------------------
#define AP 40
#define BPP 136
#define PROJ_NIT (CIN / 32)   // 16

__global__ __launch_bounds__(256) void proj_gemm(
    const float* __restrict__ x,
    const float* __restrict__ bf, const float* __restrict__ bg,
    const float* __restrict__ bh)
{
    __shared__ __nv_bfloat16 As[2][128 * AP];
    __shared__ __nv_bfloat16 Bs[2][32 * BPP];

    const int tid  = threadIdx.x;
    const int lane = tid & 31;
    const int w    = tid >> 5;
    const int m0   = blockIdx.y * 128;
    const int n0   = blockIdx.x * 128;
    const int mw   = (w >> 1) * 32;
    const int nw   = (w & 1) * 64;

    // A coordinates (4 float4/thread)
    int arow_[4], acol_[4];
    #pragma unroll
    for (int it = 0; it < 4; ++it) {
        int idx = tid + 256 * it;
        arow_[it] = idx >> 3; acol_[it] = (idx & 7) * 4;
    }
    // B advancing pointers (2 cp16/thread)
    const __nv_bfloat16* bgp[2];
    unsigned bsoff[2];
    #pragma unroll
    for (int it = 0; it < 2; ++it) {
        int idx = tid + 256 * it;
        int r = idx >> 4, c = (idx & 15) * 8;
        bgp[it]   = g_wb + (size_t)r * NPROJ + n0 + c;
        bsoff[it] = r * BPP + c;
    }

    float4 aR[4];
    auto ldg_a = [&](int k0) {
        #pragma unroll
        for (int it = 0; it < 4; ++it)
            aR[it] = *(const float4*)&x[(size_t)(m0 + arow_[it]) * CIN + k0 + acol_[it]];
    };
    auto sts_a = [&](int buf) {
        #pragma unroll
        for (int it = 0; it < 4; ++it) {
            __nv_bfloat16* d = &As[buf][arow_[it] * AP + acol_[it]];
            *(__nv_bfloat162*)&d[0] = __floats2bfloat162_rn(aR[it].x, aR[it].y);
            *(__nv_bfloat162*)&d[2] = __floats2bfloat162_rn(aR[it].z, aR[it].w);
        }
    };
    auto cp_b = [&](int buf) {
        #pragma unroll
        for (int it = 0; it < 2; ++it) {
            cp_async16(&Bs[buf][bsoff[it]], bgp[it]);
            bgp[it] += 32 * NPROJ;
        }
        asm volatile("cp.async.commit_group;");
    };

    float acc[2][8][4];
    #pragma unroll
    for (int m = 0; m < 2; ++m)
        #pragma unroll
        for (int t = 0; t < 8; ++t)
            #pragma unroll
            for (int e = 0; e < 4; ++e) acc[m][t][e] = 0.0f;

    const int lrow = (lane & 7) + 8 * ((lane >> 3) & 1);
    const int lcol = 8 * (lane >> 4);

    // Prologue
    ldg_a(0);
    cp_b(0);
    sts_a(0);

    for (int k = 0; k < PROJ_NIT; ++k) {
        const int buf = k & 1;
        if (k + 1 < PROJ_NIT) {
            ldg_a((k + 1) * 32);
            cp_b(buf ^ 1);
            asm volatile("cp.async.wait_group 1;");
        } else {
            asm volatile("cp.async.wait_group 0;");
        }
        __syncthreads();

        unsigned af[2][2][4];
        #pragma unroll
        for (int m = 0; m < 2; ++m)
            #pragma unroll
            for (int kb = 0; kb < 2; ++kb)
                ldsm_x4(smaddr(&As[buf][(mw + m * 16 + lrow) * AP + kb * 16 + lcol]),
                        af[m][kb]);
        #pragma unroll
        for (int kb = 0; kb < 2; ++kb) {
            #pragma unroll
            for (int j = 0; j < 4; ++j) {
                unsigned bv[4];
                ldsm_x4_trans(smaddr(&Bs[buf][(kb * 16 + lrow) * BPP + nw + 16 * j + lcol]), bv);
                #pragma unroll
                for (int m = 0; m < 2; ++m) {
                    mma16816(acc[m][2 * j + 0], af[m][kb], bv + 0);
                    mma16816(acc[m][2 * j + 1], af[m][kb], bv + 2);
                }
            }
        }
        if (k + 1 < PROJ_NIT) sts_a(buf ^ 1);
    }

    // Epilogue: split-store + bias (+log2e prescale for g)
    const int gc = n0 + nw;
    __nv_bfloat16* out;
    const float* bias;
    int ldo, coff;
    float scl = 1.0f;
    if (gc < 64)        { out = g_fb; bias = bf; ldo = DQK; coff = 0; }
    else if (gc < 128)  { out = g_gb; bias = bg; ldo = DQK; coff = 64; scl = LOG2E; }
    else                { out = g_hb; bias = bh; ldo = DV;  coff = 128; }

    const int crow = lane >> 2;
    const int ccol = 2 * (lane & 3);
    #pragma unroll
    for (int m = 0; m < 2; ++m) {
        int r1 = m0 + mw + m * 16 + crow;
        int r2 = r1 + 8;
        #pragma unroll
        for (int t = 0; t < 8; ++t) {
            int col = gc - coff + 8 * t + ccol;
            float b0 = bias[col], b1 = bias[col + 1];
            *(__nv_bfloat162*)&out[(size_t)r1 * ldo + col] =
                __floats2bfloat162_rn((acc[m][t][0] + b0) * scl, (acc[m][t][1] + b1) * scl);
            *(__nv_bfloat162*)&out[(size_t)r2 * ldo + col] =
                __floats2bfloat162_rn((acc[m][t][2] + b0) * scl, (acc[m][t][3] + b1) * scl);
        }
    }
}

// ---------------------------------------------------------------------------
// Kernel 2: flash attention (EXACT R11 version — best known: triple-buffered
// K/V, single __syncthreads per tile, unnormalized exp2 softmax, register P).
// ---------------------------------------------------------------------------
#define QP 72
#define KBUF 9216     // 64*72*2
#define VBUF 33792    // 64*264*2
#define VP 264

#define SM_Q  0                        // 18432
#define SM_K  18432                    // 3 x 9216
#define SM_V  (18432 + 3 * KBUF)       // 3 x 33792
#define ATTN_SMEM_BYTES (18432 + 3 * KBUF + 3 * VBUF)   // 147456

#define NTILE (NTOK / 64)   // 64

__global__ __launch_bounds__(256, 1) void attn_kernel()
{
    extern __shared__ char sm[];
    __nv_bfloat16* Qs = (__nv_bfloat16*)(sm + SM_Q);

    const int tid  = threadIdx.x;
    const int lane = tid & 31;
    const int w    = tid >> 5;
    const int b    = blockIdx.y;
    const int q0   = blockIdx.x * 128;

    const __nv_bfloat16* Fb = g_fb + (size_t)b * NTOK * DQK;
    const __nv_bfloat16* Gb = g_gb + (size_t)b * NTOK * DQK;
    const __nv_bfloat16* Hb = g_hb + (size_t)b * NTOK * DV;

    int kr[2], kc[2], vr[8], vc[8];
    #pragma unroll
    for (int it = 0; it < 2; ++it) {
        int idx = tid + 256 * it;
        kr[it] = idx >> 3; kc[it] = (idx & 7) * 8;
    }
    #pragma unroll
    for (int it = 0; it < 8; ++it) {
        int idx = tid + 256 * it;
        vr[it] = idx >> 5; vc[it] = (idx & 31) * 8;
    }

    auto prefetch = [&](int kt) {
        const __nv_bfloat16* Fk = Fb + (size_t)kt * 64 * DQK;
        const __nv_bfloat16* Hk = Hb + (size_t)kt * 64 * DV;
        const int s = kt % 3;
        __nv_bfloat16* Kd = (__nv_bfloat16*)(sm + SM_K + s * KBUF);
        __nv_bfloat16* Vd = (__nv_bfloat16*)(sm + SM_V + s * VBUF);
        #pragma unroll
        for (int it = 0; it < 2; ++it)
            cp_async16(&Kd[kr[it] * QP + kc[it]], &Fk[(size_t)kr[it] * DQK + kc[it]]);
        #pragma unroll
        for (int it = 0; it < 8; ++it)
            cp_async16(&Vd[vr[it] * VP + vc[it]], &Hk[(size_t)vr[it] * DV + vc[it]]);
        asm volatile("cp.async.commit_group;");
    };

    // Load Q tile (128 x 64 bf16)
    #pragma unroll
    for (int it = 0; it < 4; ++it) {
        int idx = tid + 256 * it;
        int r = idx >> 3, c = (idx & 7) * 8;
        *(uint4*)&Qs[r * QP + c] = *(const uint4*)&Gb[(size_t)(q0 + r) * DQK + c];
    }

    // Prologue: 2 tiles in flight
    prefetch(0);
    prefetch(1);
    __syncthreads();   // Q visible

    const int arow   = w * 16 + (lane & 7) + 8 * ((lane >> 3) & 1);
    const int acolhi = 8 * (lane >> 4);
    unsigned qa[4][4];
    #pragma unroll
    for (int kb = 0; kb < 4; ++kb)
        ldsm_x4(smaddr(&Qs[arow * QP + kb * 16 + acolhi]), qa[kb]);

    float oacc[32][4];
    #pragma unroll
    for (int t = 0; t < 32; ++t)
        #pragma unroll
        for (int e = 0; e < 4; ++e) oacc[t][e] = 0.0f;

    float l0 = 0.0f, l1 = 0.0f;

    for (int kt = 0; kt < NTILE; ++kt) {
        const int s = kt % 3;

        if (kt < NTILE - 1) asm volatile("cp.async.wait_group 1;");
        else                asm volatile("cp.async.wait_group 0;");
        __syncthreads();   // single barrier per tile

        if (kt + 2 < NTILE) prefetch(kt + 2);

        const __nv_bfloat16* Ks = (const __nv_bfloat16*)(sm + SM_K + s * KBUF);
        const __nv_bfloat16* Vs = (const __nv_bfloat16*)(sm + SM_V + s * VBUF);

        // ---- S = Q @ K^T : 16 rows x 64 cols per warp ----
        float sacc[8][4];
        #pragma unroll
        for (int t = 0; t < 8; ++t)
            #pragma unroll
            for (int e = 0; e < 4; ++e) sacc[t][e] = 0.0f;

        #pragma unroll
        for (int kb = 0; kb < 4; ++kb) {
            const int kcc = kb * 16 + 8 * ((lane >> 3) & 1);
            #pragma unroll
            for (int h = 0; h < 4; ++h) {
                int nrow = h * 16 + (lane & 7) + 8 * (lane >> 4);
                unsigned bb[4];
                ldsm_x4(smaddr(&Ks[nrow * QP + kcc]), bb);
                mma16816(sacc[2 * h + 0], qa[kb], bb + 0);
                mma16816(sacc[2 * h + 1], qa[kb], bb + 2);
            }
        }

        // ---- unnormalized exp2 + l accumulation + P pack ----
        unsigned pa[4][4];
        #pragma unroll
        for (int j = 0; j < 8; ++j) {
            sacc[j][0] = exp2a(sacc[j][0]);
            sacc[j][1] = exp2a(sacc[j][1]);
            sacc[j][2] = exp2a(sacc[j][2]);
            sacc[j][3] = exp2a(sacc[j][3]);
            l0 += sacc[j][0] + sacc[j][1];
            l1 += sacc[j][2] + sacc[j][3];
        }
        #pragma unroll
        for (int kb = 0; kb < 4; ++kb) {
            pa[kb][0] = packbf(sacc[2 * kb][0],     sacc[2 * kb][1]);
            pa[kb][1] = packbf(sacc[2 * kb][2],     sacc[2 * kb][3]);
            pa[kb][2] = packbf(sacc[2 * kb + 1][0], sacc[2 * kb + 1][1]);
            pa[kb][3] = packbf(sacc[2 * kb + 1][2], sacc[2 * kb + 1][3]);
        }

        // ---- O += P @ V : 16 rows x 256 cols per warp ----
        #pragma unroll
        for (int kb = 0; kb < 4; ++kb) {
            int vrow = kb * 16 + (lane & 7) + 8 * ((lane >> 3) & 1);
            #pragma unroll
            for (int j = 0; j < 16; ++j) {
                unsigned bv[4];
                ldsm_x4_trans(smaddr(&Vs[vrow * VP + 16 * j + 8 * (lane >> 4)]), bv);
                mma16816(oacc[2 * j + 0], pa[kb], bv + 0);
                mma16816(oacc[2 * j + 1], pa[kb], bv + 2);
            }
        }
    }

    l0 += __shfl_xor_sync(0xffffffffu, l0, 1);
    l0 += __shfl_xor_sync(0xffffffffu, l0, 2);
    l1 += __shfl_xor_sync(0xffffffffu, l1, 1);
    l1 += __shfl_xor_sync(0xffffffffu, l1, 2);

    const int crow = lane >> 2;
    const int ccol = 2 * (lane & 3);
    __nv_bfloat16* Op = g_ob + (size_t)b * NTOK * DV;
    const int r1 = q0 + w * 16 + crow;
    const int r2 = r1 + 8;
    const float inv0 = 1.0f / l0;
    const float inv1 = 1.0f / l1;
    #pragma unroll
    for (int t = 0; t < 32; ++t) {
        int c = 8 * t + ccol;
        *(__nv_bfloat162*)&Op[(size_t)r1 * DV + c] =
            __floats2bfloat162_rn(oacc[t][0] * inv0, oacc[t][1] * inv0);
        *(__nv_bfloat162*)&Op[(size_t)r2 * DV + c] =
            __floats2bfloat162_rn(oacc[t][2] * inv1, oacc[t][3] * inv1);
    }
}

// ---------------------------------------------------------------------------
// Kernel 3: output projection — BOTH operands bf16 via cp.async (A from g_ob,
// B from g_wob), one commit+wait per iteration. Residual epilogue.
// ---------------------------------------------------------------------------
#define OUT_NIT (DV / 32)    // 8

__global__ __launch_bounds__(256) void outproj_gemm(
    const float* __restrict__ x,
    const float* __restrict__ bo, const float* __restrict__ gamma,
    float* __restrict__ out)
{
    __shared__ __nv_bfloat16 As[2][128 * AP];
    __shared__ __nv_bfloat16 Bs[2][32 * BPP];

    const int tid  = threadIdx.x;
    const int lane = tid & 31;
    const int w    = tid >> 5;
    const int m0   = blockIdx.y * 128;
    const int n0   = blockIdx.x * 128;
    const int mw   = (w >> 1) * 32;
    const int nw   = (w & 1) * 64;

    const __nv_bfloat16* agp[2];
    unsigned asmoff[2];
    const __nv_bfloat16* bgp[2];
    unsigned bsoff[2];
    #pragma unroll
    for (int it = 0; it < 2; ++it) {
        int idx = tid + 256 * it;
        int r = idx >> 2, c = (idx & 3) * 8;
        agp[it]    = g_ob + (size_t)(m0 + r) * DV + c;
        asmoff[it] = r * AP + c;
        int rb = idx >> 4, cb = (idx & 15) * 8;
        bgp[it]   = g_wob + (size_t)rb * CIN + n0 + cb;
        bsoff[it] = rb * BPP + cb;
    }

    auto cp_ab = [&](int buf) {
        #pragma unroll
        for (int it = 0; it < 2; ++it) {
            cp_async16(&As[buf][asmoff[it]], agp[it]);
            agp[it] += 32;
        }
        #pragma unroll
        for (int it = 0; it < 2; ++it) {
            cp_async16(&Bs[buf][bsoff[it]], bgp[it]);
            bgp[it] += 32 * CIN;
        }
        asm volatile("cp.async.commit_group;");
    };

    float acc[2][8][4];
    #pragma unroll
    for (int m = 0; m < 2; ++m)
        #pragma unroll
        for (int t = 0; t < 8; ++t)
            #pragma unroll
            for (int e = 0; e < 4; ++e) acc[m][t][e] = 0.0f;

    const int lrow = (lane & 7) + 8 * ((lane >> 3) & 1);
    const int lcol = 8 * (lane >> 4);

    cp_ab(0);

    for (int k = 0; k < OUT_NIT; ++k) {
        const int buf = k & 1;
        if (k + 1 < OUT_NIT) {
            cp_ab(buf ^ 1);
            asm volatile("cp.async.wait_group 1;");
        } else {
            asm volatile("cp.async.wait_group 0;");
        }
        __syncthreads();

        unsigned af[2][2][4];
        #pragma unroll
        for (int m = 0; m < 2; ++m)
            #pragma unroll
            for (int kb = 0; kb < 2; ++kb)
                ldsm_x4(smaddr(&As[buf][(mw + m * 16 + lrow) * AP + kb * 16 + lcol]),
                        af[m][kb]);
        #pragma unroll
        for (int kb = 0; kb < 2; ++kb) {
            #pragma unroll
            for (int j = 0; j < 4; ++j) {
                unsigned bv[4];
                ldsm_x4_trans(smaddr(&Bs[buf][(kb * 16 + lrow) * BPP + nw + 16 * j + lcol]), bv);
                #pragma unroll
                for (int m = 0; m < 2; ++m) {
                    mma16816(acc[m][2 * j + 0], af[m][kb], bv + 0);
                    mma16816(acc[m][2 * j + 1], af[m][kb], bv + 2);
                }
            }
        }
    }

    const float ga = gamma[0];
    const int crow = lane >> 2;
    const int ccol = 2 * (lane & 3);
    #pragma unroll
    for (int m = 0; m < 2; ++m) {
        int r1 = m0 + mw + m * 16 + crow;
        int r2 = r1 + 8;
        #pragma unroll
        for (int t = 0; t < 8; ++t) {
            int col = n0 + nw + 8 * t + ccol;
            float b0 = bo[col], b1 = bo[col + 1];
            size_t i1 = (size_t)r1 * CIN + col;
            size_t i2 = (size_t)r2 * CIN + col;
            float2 x1 = *(const float2*)&x[i1];
            float2 x2 = *(const float2*)&x[i2];
            *(float2*)&out[i1] = make_float2(x1.x + ga * (acc[m][t][0] + b0),
                                             x1.y + ga * (acc[m][t][1] + b1));
            *(float2*)&out[i2] = make_float2(x2.x + ga * (acc[m][t][2] + b0),
                                             x2.y + ga * (acc[m][t][3] + b1));
        }
    }
}

// ---------------------------------------------------------------------------
extern "C" void kernel_launch(void* const* d_in, const int* in_sizes, int n_in,
                              void* d_out, int out_size)
{
    const float* x     = (const float*)d_in[0];
    const float* Wf    = (const float*)d_in[1];
    const float* bf    = (const float*)d_in[2];
    const float* Wg    = (const float*)d_in[3];
    const float* bg    = (const float*)d_in[4];
    const float* Wh    = (const float*)d_in[5];
    const float* bh    = (const float*)d_in[6];
    const float* Wo    = (const float*)d_in[7];
    const float* bo    = (const float*)d_in[8];
    const float* gamma = (const float*)d_in[9];
    float* out = (float*)d_out;

    cudaFuncSetAttribute(attn_kernel,
                         cudaFuncAttributeMaxDynamicSharedMemorySize,
                         ATTN_SMEM_BYTES);

    pack_w_kernel<<<(CIN * NPROJ + DV * CIN) / 512, 512>>>(Wf, Wg, Wh, Wo);
    proj_gemm<<<dim3(3, 128), 256>>>(x, bf, bg, bh);
    attn_kernel<<<dim3(NTOK / 128, BATCH), 256, ATTN_SMEM_BYTES>>>();
    outproj_gemm<<<dim3(4, 128), 256>>>(x, bo, gamma, out);
}